// round 1
// baseline (speedup 1.0000x reference)
#include <cuda_runtime.h>
#include <math.h>

#define N_ANCH   8400
#define TOPK     10
#define ROI      3
#define NCHAN    256
#define FH       20
#define IMGSZ_F  640.0f
#define CONF_TH  0.25f
#define IOU_TH   0.45f
#define NMS_THREADS 1024

// Scratch (no allocations allowed): decoded boxes SoA + per-keep record.
__device__ float g_bx1[N_ANCH];
__device__ float g_by1[N_ANCH];
__device__ float g_bx2[N_ANCH];
__device__ float g_by2[N_ANCH];
// keep record: x1,y1,x2,y2,ok per kept slot
__device__ float g_keep[TOPK][5];

// ---------------------------------------------------------------------------
// Kernel 1: decode + greedy NMS (single block, 1024 threads).
// Scores live in shared memory; suppression sets them to -inf.
// ---------------------------------------------------------------------------
__global__ __launch_bounds__(NMS_THREADS) void nms_kernel(const float* __restrict__ pred)
{
    __shared__ float s[N_ANCH];         // masked scores
    __shared__ float r_val[32];
    __shared__ int   r_idx[32];
    __shared__ float bsel[5];           // selected box x1,y1,x2,y2, has-flag

    const int tid  = threadIdx.x;
    const int lane = tid & 31;
    const int wid  = tid >> 5;

    const float* __restrict__ pcx = pred;
    const float* __restrict__ pcy = pred + 1 * N_ANCH;
    const float* __restrict__ pw  = pred + 2 * N_ANCH;
    const float* __restrict__ ph  = pred + 3 * N_ANCH;
    const float* __restrict__ pcf = pred + 4 * N_ANCH;

    // Decode: coalesced loads, boxes to global SoA, masked scores to smem.
    for (int a = tid; a < N_ANCH; a += NMS_THREADS) {
        float x = pcx[a], y = pcy[a], w = pw[a], h = ph[a], cf = pcf[a];
        g_bx1[a] = x - w * 0.5f;
        g_by1[a] = y - h * 0.5f;
        g_bx2[a] = x + w * 0.5f;
        g_by2[a] = y + h * 0.5f;
        s[a] = (cf >= CONF_TH) ? cf : -INFINITY;
    }
    __syncthreads();

    for (int t = 0; t < TOPK; t++) {
        // ---- block argmax (first-index tie-break, matching jnp.argmax) ----
        float bv = -INFINITY;
        int   bi = 0x7fffffff;
        for (int a = tid; a < N_ANCH; a += NMS_THREADS) {
            float v = s[a];
            if (v > bv || (v == bv && a < bi)) { bv = v; bi = a; }
        }
        #pragma unroll
        for (int o = 16; o; o >>= 1) {
            float ov = __shfl_down_sync(0xffffffffu, bv, o);
            int   oi = __shfl_down_sync(0xffffffffu, bi, o);
            if (ov > bv || (ov == bv && oi < bi)) { bv = ov; bi = oi; }
        }
        if (lane == 0) { r_val[wid] = bv; r_idx[wid] = bi; }
        __syncthreads();
        if (wid == 0) {
            bv = r_val[lane]; bi = r_idx[lane];
            #pragma unroll
            for (int o = 16; o; o >>= 1) {
                float ov = __shfl_down_sync(0xffffffffu, bv, o);
                int   oi = __shfl_down_sync(0xffffffffu, bi, o);
                if (ov > bv || (ov == bv && oi < bi)) { bv = ov; bi = oi; }
            }
            if (lane == 0) {
                if (bv > -INFINITY) {            // has = masked[i] > -inf
                    float x1 = g_bx1[bi], y1 = g_by1[bi];
                    float x2 = g_bx2[bi], y2 = g_by2[bi];
                    bsel[0] = x1; bsel[1] = y1; bsel[2] = x2; bsel[3] = y2;
                    bsel[4] = 1.0f;
                    s[bi]   = -INFINITY;         // (ar == i) suppression
                    g_keep[t][0] = x1; g_keep[t][1] = y1;
                    g_keep[t][2] = x2; g_keep[t][3] = y2;
                    g_keep[t][4] = 1.0f;
                } else {
                    bsel[4] = 0.0f;
                    g_keep[t][0] = 0.0f; g_keep[t][1] = 0.0f;
                    g_keep[t][2] = 0.0f; g_keep[t][3] = 0.0f;
                    g_keep[t][4] = 0.0f;
                }
            }
        }
        __syncthreads();

        // ---- suppression pass ----
        if (bsel[4] > 0.0f) {
            const float x1 = bsel[0], y1 = bsel[1], x2 = bsel[2], y2 = bsel[3];
            const float a1 = fmaxf(x2 - x1, 0.0f) * fmaxf(y2 - y1, 0.0f);
            for (int a = tid; a < N_ANCH; a += NMS_THREADS) {
                if (s[a] == -INFINITY) continue;     // already invalid
                float bx1 = g_bx1[a], by1 = g_by1[a];
                float bx2 = g_bx2[a], by2 = g_by2[a];
                float lx = fmaxf(x1, bx1), ly = fmaxf(y1, by1);
                float rx = fminf(x2, bx2), ry = fminf(y2, by2);
                float iw = fmaxf(rx - lx, 0.0f), ih = fmaxf(ry - ly, 0.0f);
                float inter = iw * ih;
                float a2 = fmaxf(bx2 - bx1, 0.0f) * fmaxf(by2 - by1, 0.0f);
                float uni = fmaxf(a1 + a2 - inter, 1e-9f);
                if (inter / uni > IOU_TH) s[a] = -INFINITY;
            }
        }
        __syncthreads();
    }
}

// ---------------------------------------------------------------------------
// Kernel 2: ROI-align tokens. grid = TOPK*9 blocks, block = 256 threads.
// blockIdx -> (k, roi point p); threadIdx.x -> channel c.
// ---------------------------------------------------------------------------
__global__ __launch_bounds__(NCHAN) void roi_kernel(const float* __restrict__ feat,
                                                    float* __restrict__ out)
{
    const int b = blockIdx.x;
    const int k = b / (ROI * ROI);
    const int p = b % (ROI * ROI);
    const int c = threadIdx.x;

    float* o = out + (k * (ROI * ROI) + p) * NCHAN + c;

    const float ok = g_keep[k][4];
    if (ok == 0.0f) { *o = 0.0f; return; }

    const float scale = (float)FH / IMGSZ_F;
    const float sx1 = g_keep[k][0] * scale;
    const float sy1 = g_keep[k][1] * scale;
    const float sx2 = g_keep[k][2] * scale;
    const float sy2 = g_keep[k][3] * scale;

    const float bw = fmaxf(sx2 - sx1, 1e-6f) / (float)ROI;
    const float bh = fmaxf(sy2 - sy1, 1e-6f) / (float)ROI;

    const int gy = p / ROI;
    const int gx = p % ROI;
    const float yg = sy1 + ((float)gy + 0.5f) * bh;
    const float xg = sx1 + ((float)gx + 0.5f) * bw;

    const float fy = floorf(yg);
    const float fx = floorf(xg);
    const float wy = yg - fy;
    const float wx = xg - fx;

    int y0 = min(max((int)fy, 0), FH - 1);
    int x0 = min(max((int)fx, 0), FH - 1);
    int y1i = min(y0 + 1, FH - 1);
    int x1i = min(x0 + 1, FH - 1);

    const float* f = feat + c * (FH * FH);
    float v00 = f[y0  * FH + x0 ];
    float v01 = f[y0  * FH + x1i];
    float v10 = f[y1i * FH + x0 ];
    float v11 = f[y1i * FH + x1i];

    float val = v00 * (1.0f - wy) * (1.0f - wx)
              + v01 * (1.0f - wy) * wx
              + v10 * wy * (1.0f - wx)
              + v11 * wy * wx;
    *o = val;
}

// ---------------------------------------------------------------------------
extern "C" void kernel_launch(void* const* d_in, const int* in_sizes, int n_in,
                              void* d_out, int out_size)
{
    // metadata order: pred (1*5*8400 = 42000), feat (1*256*20*20 = 102400).
    const float* pred = (const float*)d_in[0];
    const float* feat = (const float*)d_in[1];
    if (n_in >= 2 && in_sizes[0] != 5 * N_ANCH) {   // defensive swap on sizes
        pred = (const float*)d_in[1];
        feat = (const float*)d_in[0];
    }
    float* out = (float*)d_out;

    nms_kernel<<<1, NMS_THREADS>>>(pred);
    roi_kernel<<<TOPK * ROI * ROI, NCHAN>>>(feat, out);
}

// round 2
// speedup vs baseline: 1.1587x; 1.1587x over previous
#include <cuda_runtime.h>
#include <math.h>

#define N_ANCH   8400
#define TOPK     10
#define ROI      3
#define NCHAN    256
#define FH       20
#define CONF_TH  0.25f
#define IOU_TH   0.45f
#define NT       1024
#define CAND_MAX 1664
#define NBANDS   10

// ---------------------------------------------------------------------------
// Fused decode + banded greedy NMS + ROI-align. Single block.
//
// Equivalence to reference greedy NMS: processing candidates in descending
// score order, a candidate is selected iff no previously-selected box
// suppresses it (IoU > 0.45). Bands partition [0.25, 1.0); a lower band is
// only materialized when fewer than TOPK keeps exist among all higher bands,
// so selections never depend on unmaterialized (strictly lower-scoring)
// candidates. Tie-break on equal scores: smaller original anchor index
// (matches jnp.argmax).
// ---------------------------------------------------------------------------
__global__ __launch_bounds__(NT) void fused_kernel(const float* __restrict__ pred,
                                                   const float* __restrict__ feat,
                                                   float* __restrict__ out)
{
    __shared__ float c_score[CAND_MAX];
    __shared__ int   c_idx[CAND_MAX];
    __shared__ float c_x1[CAND_MAX], c_y1[CAND_MAX];
    __shared__ float c_x2[CAND_MAX], c_y2[CAND_MAX];
    __shared__ int   s_count, s_old, s_keeps;
    __shared__ float s_keep[TOPK][5];       // x1,y1,x2,y2,ok

    const int tid = threadIdx.x;

    const float* __restrict__ pcx = pred;
    const float* __restrict__ pcy = pred + N_ANCH;
    const float* __restrict__ pw  = pred + 2 * N_ANCH;
    const float* __restrict__ ph  = pred + 3 * N_ANCH;
    const float* __restrict__ pcf = pred + 4 * N_ANCH;

    if (tid == 0) { s_count = 0; s_keeps = 0; }

    // Warm L2 with feat (400 KB = 3200 lines) while NMS runs. Fire-and-forget.
    for (int i = tid; i < (NCHAN * FH * FH * 4) / 128; i += NT) {
        asm volatile("prefetch.global.L2 [%0];" :: "l"(((const char*)feat) + i * 128));
    }

    const float lo_tab[NBANDS] = {0.99f, 0.93f, 0.87f, 0.80f, 0.72f,
                                  0.64f, 0.55f, 0.45f, 0.35f, 0.25f};
    float hi = 2.0f;

    for (int band = 0; band < NBANDS; band++) {
        __syncthreads();
        if (s_keeps >= TOPK) break;
        if (tid == 0) s_old = s_count;
        __syncthreads();

        // ---- compact this band's candidates into the pool ----
        const float lo = lo_tab[band];
        for (int a = tid; a < N_ANCH; a += NT) {
            float cf = pcf[a];
            if (cf >= lo && cf < hi) {
                int slot = atomicAdd(&s_count, 1);
                if (slot < CAND_MAX) {
                    float x = pcx[a], y = pcy[a];
                    float wh = pw[a] * 0.5f, hh = ph[a] * 0.5f;
                    c_score[slot] = cf;
                    c_idx[slot]   = a;
                    c_x1[slot] = x - wh; c_y1[slot] = y - hh;
                    c_x2[slot] = x + wh; c_y2[slot] = y + hh;
                }
            }
        }
        __syncthreads();
        hi = lo;

        // ---- warp 0: suppress new entries vs. existing keeps, then select ----
        if (tid < 32) {
            int count = min(s_count, CAND_MAX);
            int keeps = s_keeps;
            int nold  = s_old;

            for (int ki = 0; ki < keeps; ki++) {
                float kx1 = s_keep[ki][0], ky1 = s_keep[ki][1];
                float kx2 = s_keep[ki][2], ky2 = s_keep[ki][3];
                float a1 = fmaxf(kx2 - kx1, 0.f) * fmaxf(ky2 - ky1, 0.f);
                for (int j = nold + tid; j < count; j += 32) {
                    float lx = fmaxf(kx1, c_x1[j]), ly = fmaxf(ky1, c_y1[j]);
                    float rx = fminf(kx2, c_x2[j]), ry = fminf(ky2, c_y2[j]);
                    float inter = fmaxf(rx - lx, 0.f) * fmaxf(ry - ly, 0.f);
                    float a2 = fmaxf(c_x2[j] - c_x1[j], 0.f) * fmaxf(c_y2[j] - c_y1[j], 0.f);
                    if (inter / fmaxf(a1 + a2 - inter, 1e-9f) > IOU_TH)
                        c_score[j] = -INFINITY;
                }
            }
            __syncwarp();

            while (keeps < TOPK) {
                // warp argmax, tie-break on smaller original anchor index
                float bv = -INFINITY; int borig = 0x7fffffff; int bslot = 0;
                for (int j = tid; j < count; j += 32) {
                    float v = c_score[j];
                    int   oi = c_idx[j];
                    if (v > bv || (v == bv && oi < borig)) { bv = v; borig = oi; bslot = j; }
                }
                #pragma unroll
                for (int o = 16; o; o >>= 1) {
                    float ov    = __shfl_xor_sync(0xffffffffu, bv, o);
                    int   oorig = __shfl_xor_sync(0xffffffffu, borig, o);
                    int   oslot = __shfl_xor_sync(0xffffffffu, bslot, o);
                    if (ov > bv || (ov == bv && oorig < borig)) { bv = ov; borig = oorig; bslot = oslot; }
                }
                if (bv == -INFINITY) break;   // pool exhausted -> need next band

                float kx1 = c_x1[bslot], ky1 = c_y1[bslot];
                float kx2 = c_x2[bslot], ky2 = c_y2[bslot];
                if (tid == 0) {
                    s_keep[keeps][0] = kx1; s_keep[keeps][1] = ky1;
                    s_keep[keeps][2] = kx2; s_keep[keeps][3] = ky2;
                    s_keep[keeps][4] = 1.f;
                }
                // suppress pool vs. the new keep (self-IoU = 1 covers ar==i)
                float a1 = fmaxf(kx2 - kx1, 0.f) * fmaxf(ky2 - ky1, 0.f);
                for (int j = tid; j < count; j += 32) {
                    if (c_score[j] == -INFINITY) continue;
                    float lx = fmaxf(kx1, c_x1[j]), ly = fmaxf(ky1, c_y1[j]);
                    float rx = fminf(kx2, c_x2[j]), ry = fminf(ky2, c_y2[j]);
                    float inter = fmaxf(rx - lx, 0.f) * fmaxf(ry - ly, 0.f);
                    float a2 = fmaxf(c_x2[j] - c_x1[j], 0.f) * fmaxf(c_y2[j] - c_y1[j], 0.f);
                    if (inter / fmaxf(a1 + a2 - inter, 1e-9f) > IOU_TH)
                        c_score[j] = -INFINITY;
                }
                __syncwarp();
                keeps++;
            }
            if (tid == 0) s_keeps = keeps;
        }
    }

    __syncthreads();
    if (tid < TOPK && tid >= s_keeps) s_keep[tid][4] = 0.f;   // invalid slots
    __syncthreads();

    // ---- ROI-align: 10 boxes x 3x3 points x 256 channels, feat now L2-hot ----
    const float scale = (float)FH / 640.0f;
    for (int oi = tid; oi < TOPK * ROI * ROI * NCHAN; oi += NT) {
        int c  = oi & (NCHAN - 1);
        int pk = oi >> 8;              // k*9 + p
        int k  = pk / 9;
        int p  = pk - k * 9;

        float val = 0.f;
        if (s_keep[k][4] != 0.f) {
            float sx1 = s_keep[k][0] * scale, sy1 = s_keep[k][1] * scale;
            float sx2 = s_keep[k][2] * scale, sy2 = s_keep[k][3] * scale;
            float bw = fmaxf(sx2 - sx1, 1e-6f) / 3.0f;
            float bh = fmaxf(sy2 - sy1, 1e-6f) / 3.0f;
            int gy = p / 3, gx = p - gy * 3;
            float yg = sy1 + ((float)gy + 0.5f) * bh;
            float xg = sx1 + ((float)gx + 0.5f) * bw;
            float fy = floorf(yg), fx = floorf(xg);
            float wy = yg - fy, wx = xg - fx;
            int y0  = min(max((int)fy, 0), FH - 1);
            int x0  = min(max((int)fx, 0), FH - 1);
            int y1i = min(y0 + 1, FH - 1);
            int x1i = min(x0 + 1, FH - 1);
            const float* f = feat + c * (FH * FH);
            float v00 = f[y0  * FH + x0 ];
            float v01 = f[y0  * FH + x1i];
            float v10 = f[y1i * FH + x0 ];
            float v11 = f[y1i * FH + x1i];
            val = v00 * (1.f - wy) * (1.f - wx)
                + v01 * (1.f - wy) * wx
                + v10 * wy * (1.f - wx)
                + v11 * wy * wx;
        }
        out[oi] = val;
    }
}

// ---------------------------------------------------------------------------
extern "C" void kernel_launch(void* const* d_in, const int* in_sizes, int n_in,
                              void* d_out, int out_size)
{
    const float* pred = (const float*)d_in[0];
    const float* feat = (const float*)d_in[1];
    if (n_in >= 2 && in_sizes[0] != 5 * N_ANCH) {   // defensive swap on sizes
        pred = (const float*)d_in[1];
        feat = (const float*)d_in[0];
    }
    float* out = (float*)d_out;

    fused_kernel<<<1, NT>>>(pred, feat, out);
}

// round 4
// speedup vs baseline: 2.7295x; 2.3555x over previous
#include <cuda_runtime.h>
#include <math.h>

#define N_ANCH   8400
#define TOPK     10
#define ROI      3
#define NCHAN    256
#define FH       20
#define IOU_TH   0.45f
#define NT       256
#define CAND_MAX 1536
#define NBANDS   10

// ---------------------------------------------------------------------------
// One kernel, 90 blocks. Every block redundantly runs banded greedy NMS
// (tiny: ~84 candidates, one warp), then computes its own (k, roi-point)
// output slice of 256 channels.
//
// Greedy-NMS equivalence: candidates processed in descending score order;
// a candidate is kept iff no previously-kept box has IoU > 0.45 with it.
// Bands partition scores downward from 0.99; a lower band is materialized
// only when fewer than TOPK keeps exist among all higher bands, so results
// never depend on unmaterialized (strictly lower-scoring) anchors.
// Selection key = (score_bits << 32) | (0x7fffffff - idx): descending score,
// first-index tie-break — matches jnp.argmax. Keys are unique, so the argmax
// (and hence the keep set) is identical in every block regardless of the
// nondeterministic atomicAdd slot order.
// ---------------------------------------------------------------------------
__global__ __launch_bounds__(NT) void fused_kernel(const float* __restrict__ pred,
                                                   const float* __restrict__ feat,
                                                   float* __restrict__ out)
{
    __shared__ unsigned long long c_key[CAND_MAX];
    __shared__ float c_x1[CAND_MAX], c_y1[CAND_MAX];
    __shared__ float c_x2[CAND_MAX], c_y2[CAND_MAX];
    __shared__ int   s_count, s_old, s_keeps;
    __shared__ float s_keep[TOPK][5];       // x1,y1,x2,y2,ok

    const int tid = threadIdx.x;

    const float* __restrict__ pcx = pred;
    const float* __restrict__ pcy = pred + N_ANCH;
    const float* __restrict__ pw  = pred + 2 * N_ANCH;
    const float* __restrict__ ph  = pred + 3 * N_ANCH;
    const float4* __restrict__ pcf4 = (const float4*)(pred + 4 * N_ANCH);

    if (tid == 0) { s_count = 0; s_keeps = 0; }

    const float lo_tab[NBANDS] = {0.99f, 0.93f, 0.87f, 0.80f, 0.72f,
                                  0.64f, 0.55f, 0.45f, 0.35f, 0.25f};
    float hi = 2.0f;

    for (int band = 0; band < NBANDS; band++) {
        __syncthreads();
        if (s_keeps >= TOPK) break;
        if (tid == 0) s_old = s_count;
        __syncthreads();

        // ---- compact this band's candidates into the smem pool ----
        const float lo = lo_tab[band];
        for (int v = tid; v < N_ANCH / 4; v += NT) {
            float4 cf4 = pcf4[v];
            float cfa[4] = {cf4.x, cf4.y, cf4.z, cf4.w};
            #pragma unroll
            for (int j = 0; j < 4; j++) {
                float cf = cfa[j];
                if (cf >= lo && cf < hi) {
                    int slot = atomicAdd(&s_count, 1);
                    if (slot < CAND_MAX) {
                        int a = v * 4 + j;
                        float x = pcx[a], y = pcy[a];
                        float wh = pw[a] * 0.5f, hh = ph[a] * 0.5f;
                        c_key[slot] = ((unsigned long long)__float_as_uint(cf) << 32)
                                    | (unsigned long long)(0x7fffffffu - (unsigned)a);
                        c_x1[slot] = x - wh; c_y1[slot] = y - hh;
                        c_x2[slot] = x + wh; c_y2[slot] = y + hh;
                    }
                }
            }
        }
        __syncthreads();
        hi = lo;

        // ---- warp 0: suppress new entries vs existing keeps, then select ----
        if (tid < 32) {
            int count = min(s_count, CAND_MAX);
            int keeps = s_keeps;
            int nold  = s_old;

            for (int ki = 0; ki < keeps; ki++) {
                float kx1 = s_keep[ki][0], ky1 = s_keep[ki][1];
                float kx2 = s_keep[ki][2], ky2 = s_keep[ki][3];
                float a1 = fmaxf(kx2 - kx1, 0.f) * fmaxf(ky2 - ky1, 0.f);
                for (int j = nold + tid; j < count; j += 32) {
                    float lx = fmaxf(kx1, c_x1[j]), ly = fmaxf(ky1, c_y1[j]);
                    float rx = fminf(kx2, c_x2[j]), ry = fminf(ky2, c_y2[j]);
                    float inter = fmaxf(rx - lx, 0.f) * fmaxf(ry - ly, 0.f);
                    float a2 = fmaxf(c_x2[j] - c_x1[j], 0.f) * fmaxf(c_y2[j] - c_y1[j], 0.f);
                    if (inter / fmaxf(a1 + a2 - inter, 1e-9f) > IOU_TH)
                        c_key[j] = 0ULL;
                }
            }
            __syncwarp();

            while (keeps < TOPK) {
                // warp argmax over unique 64-bit keys
                unsigned long long bk = 0ULL;
                int bslot = 0;
                for (int j = tid; j < count; j += 32) {
                    unsigned long long k = c_key[j];
                    if (k > bk) { bk = k; bslot = j; }
                }
                #pragma unroll
                for (int o = 16; o; o >>= 1) {
                    unsigned long long ok_ = __shfl_xor_sync(0xffffffffu, bk, o);
                    int                os_ = __shfl_xor_sync(0xffffffffu, bslot, o);
                    if (ok_ > bk) { bk = ok_; bslot = os_; }
                }
                if (bk == 0ULL) break;        // pool exhausted -> next band

                float kx1 = c_x1[bslot], ky1 = c_y1[bslot];
                float kx2 = c_x2[bslot], ky2 = c_y2[bslot];
                if (tid == 0) {
                    s_keep[keeps][0] = kx1; s_keep[keeps][1] = ky1;
                    s_keep[keeps][2] = kx2; s_keep[keeps][3] = ky2;
                    s_keep[keeps][4] = 1.f;
                }
                // suppress pool vs new keep (self-IoU = 1 handles ar==i)
                float a1 = fmaxf(kx2 - kx1, 0.f) * fmaxf(ky2 - ky1, 0.f);
                for (int j = tid; j < count; j += 32) {
                    if (c_key[j] == 0ULL) continue;
                    float lx = fmaxf(kx1, c_x1[j]), ly = fmaxf(ky1, c_y1[j]);
                    float rx = fminf(kx2, c_x2[j]), ry = fminf(ky2, c_y2[j]);
                    float inter = fmaxf(rx - lx, 0.f) * fmaxf(ry - ly, 0.f);
                    float a2 = fmaxf(c_x2[j] - c_x1[j], 0.f) * fmaxf(c_y2[j] - c_y1[j], 0.f);
                    if (inter / fmaxf(a1 + a2 - inter, 1e-9f) > IOU_TH)
                        c_key[j] = 0ULL;
                }
                __syncwarp();
                keeps++;
            }
            if (tid == 0) s_keeps = keeps;
        }
    }

    __syncthreads();
    if (tid < TOPK && tid >= s_keeps) s_keep[tid][4] = 0.f;   // invalid slots
    __syncthreads();

    // ---- ROI-align: this block's (k, p) slice, 256 channels ----
    const int b = blockIdx.x;
    const int k = b / (ROI * ROI);
    const int p = b - k * (ROI * ROI);
    const int c = tid;

    float* o = out + b * NCHAN + c;

    if (s_keep[k][4] == 0.f) { *o = 0.f; return; }

    const float scale = (float)FH / 640.0f;
    const float sx1 = s_keep[k][0] * scale, sy1 = s_keep[k][1] * scale;
    const float sx2 = s_keep[k][2] * scale, sy2 = s_keep[k][3] * scale;
    const float bw = fmaxf(sx2 - sx1, 1e-6f) / (float)ROI;
    const float bh = fmaxf(sy2 - sy1, 1e-6f) / (float)ROI;

    const int gy = p / ROI;
    const int gx = p - gy * ROI;
    const float yg = sy1 + ((float)gy + 0.5f) * bh;
    const float xg = sx1 + ((float)gx + 0.5f) * bw;

    const float fy = floorf(yg), fx = floorf(xg);
    const float wy = yg - fy,    wx = xg - fx;

    int y0  = min(max((int)fy, 0), FH - 1);
    int x0  = min(max((int)fx, 0), FH - 1);
    int y1i = min(y0 + 1, FH - 1);
    int x1i = min(x0 + 1, FH - 1);

    const float* f = feat + c * (FH * FH);
    float v00 = f[y0  * FH + x0 ];
    float v01 = f[y0  * FH + x1i];
    float v10 = f[y1i * FH + x0 ];
    float v11 = f[y1i * FH + x1i];

    *o = v00 * (1.f - wy) * (1.f - wx)
       + v01 * (1.f - wy) * wx
       + v10 * wy * (1.f - wx)
       + v11 * wy * wx;
}

// ---------------------------------------------------------------------------
extern "C" void kernel_launch(void* const* d_in, const int* in_sizes, int n_in,
                              void* d_out, int out_size)
{
    const float* pred = (const float*)d_in[0];
    const float* feat = (const float*)d_in[1];
    if (n_in >= 2 && in_sizes[0] != 5 * N_ANCH) {   // defensive swap on sizes
        pred = (const float*)d_in[1];
        feat = (const float*)d_in[0];
    }
    float* out = (float*)d_out;

    fused_kernel<<<TOPK * ROI * ROI, NT>>>(pred, feat, out);
}

// round 5
// speedup vs baseline: 3.0062x; 1.1014x over previous
#include <cuda_runtime.h>
#include <math.h>

#define N_ANCH   8400
#define TOPK     10
#define ROI      3
#define NCHAN    256
#define FH       20
#define IOU_TH   0.45f
#define NT       256
#define CAND_MAX 1536
#define NBANDS   10
#define R_CAP    8          // register slots per lane; warp capacity 256

// ---------------------------------------------------------------------------
// One kernel, 90 blocks. Every block redundantly runs banded greedy NMS,
// then computes its own (k, roi-point) slice of 256 channels.
//
// NMS equivalence (see R2-R4 notes): descending-score greedy with bands;
// a lower band is materialized only when keeps < TOPK. Selection key
// (score_bits<<32)|(0x7fffffff-idx) is unique -> identical keep set in every
// block regardless of atomicAdd slot order; first-index tie-break matches
// jnp.argmax.
//
// R5: (1) all 5 pred rows loaded unconditionally as float4 (one memory
// round-trip, MLP ~45); (2) selection loop register-resident in warp 0
// (<=256 candidates; smem fallback above that), argmax xor-reduction
// carries the box, suppression in registers. Keys written back to smem at
// band exit so multi-band inputs stay exact.
// ---------------------------------------------------------------------------
__global__ __launch_bounds__(NT) void fused_kernel(const float* __restrict__ pred,
                                                   const float* __restrict__ feat,
                                                   float* __restrict__ out)
{
    __shared__ unsigned long long c_key[CAND_MAX];
    __shared__ float4 c_box[CAND_MAX];                // x1,y1,x2,y2
    __shared__ int    s_count, s_old, s_keeps;
    __shared__ float4 s_kbox[TOPK];
    __shared__ float  s_kok[TOPK];

    const int tid  = threadIdx.x;
    const int lane = tid & 31;

    const float4* __restrict__ px4 = (const float4*)(pred);
    const float4* __restrict__ py4 = (const float4*)(pred + N_ANCH);
    const float4* __restrict__ pw4 = (const float4*)(pred + 2 * N_ANCH);
    const float4* __restrict__ ph4 = (const float4*)(pred + 3 * N_ANCH);
    const float4* __restrict__ pc4 = (const float4*)(pred + 4 * N_ANCH);

    if (tid == 0) { s_count = 0; s_keeps = 0; }

    const float lo_tab[NBANDS] = {0.99f, 0.93f, 0.87f, 0.80f, 0.72f,
                                  0.64f, 0.55f, 0.45f, 0.35f, 0.25f};
    float hi = 2.0f;

    for (int band = 0; band < NBANDS; band++) {
        __syncthreads();
        if (s_keeps >= TOPK) break;
        if (tid == 0) s_old = s_count;
        __syncthreads();

        // ---- compaction: all 5 rows loaded together (single round trip) ----
        const float lo = lo_tab[band];
        for (int v = tid; v < N_ANCH / 4; v += NT) {
            float4 cf = pc4[v];
            float4 xx = px4[v], yy = py4[v], ww = pw4[v], hh = ph4[v];
            float cfa[4] = {cf.x, cf.y, cf.z, cf.w};
            float xa [4] = {xx.x, xx.y, xx.z, xx.w};
            float ya [4] = {yy.x, yy.y, yy.z, yy.w};
            float wa [4] = {ww.x, ww.y, ww.z, ww.w};
            float ha [4] = {hh.x, hh.y, hh.z, hh.w};
            #pragma unroll
            for (int j = 0; j < 4; j++) {
                float c = cfa[j];
                if (c >= lo && c < hi) {
                    int slot = atomicAdd(&s_count, 1);
                    if (slot < CAND_MAX) {
                        int a = v * 4 + j;
                        float wh = wa[j] * 0.5f, hh2 = ha[j] * 0.5f;
                        c_key[slot] = ((unsigned long long)__float_as_uint(c) << 32)
                                    | (unsigned long long)(0x7fffffffu - (unsigned)a);
                        c_box[slot] = make_float4(xa[j] - wh, ya[j] - hh2,
                                                  xa[j] + wh, ya[j] + hh2);
                    }
                }
            }
        }
        __syncthreads();
        hi = lo;

        if (tid < 32) {
            int count = min(s_count, CAND_MAX);
            int keeps = s_keeps;
            int nold  = s_old;

            if (count <= 32 * R_CAP) {
                // ================= register-resident path =================
                unsigned long long k[R_CAP];
                float4 bx[R_CAP];
                #pragma unroll
                for (int r = 0; r < R_CAP; r++) {
                    int j = r * 32 + lane;
                    if (j < count) { k[r] = c_key[j]; bx[r] = c_box[j]; }
                    else k[r] = 0ULL;
                }

                // suppress new entries vs existing keeps (multi-band only)
                for (int ki = 0; ki < keeps; ki++) {
                    float4 kb = s_kbox[ki];
                    float a1 = fmaxf(kb.z - kb.x, 0.f) * fmaxf(kb.w - kb.y, 0.f);
                    #pragma unroll
                    for (int r = 0; r < R_CAP; r++) {
                        int j = r * 32 + lane;
                        if (j >= nold && k[r] != 0ULL) {
                            float lx = fmaxf(kb.x, bx[r].x), ly = fmaxf(kb.y, bx[r].y);
                            float rx = fminf(kb.z, bx[r].z), ry = fminf(kb.w, bx[r].w);
                            float inter = fmaxf(rx - lx, 0.f) * fmaxf(ry - ly, 0.f);
                            float a2 = fmaxf(bx[r].z - bx[r].x, 0.f) * fmaxf(bx[r].w - bx[r].y, 0.f);
                            if (inter / fmaxf(a1 + a2 - inter, 1e-9f) > IOU_TH) k[r] = 0ULL;
                        }
                    }
                }

                while (keeps < TOPK) {
                    unsigned long long bk = 0ULL;
                    float4 bb = make_float4(0.f, 0.f, 0.f, 0.f);
                    #pragma unroll
                    for (int r = 0; r < R_CAP; r++)
                        if (k[r] > bk) { bk = k[r]; bb = bx[r]; }
                    #pragma unroll
                    for (int o = 16; o; o >>= 1) {
                        unsigned long long ok_ = __shfl_xor_sync(0xffffffffu, bk, o);
                        float ox1 = __shfl_xor_sync(0xffffffffu, bb.x, o);
                        float oy1 = __shfl_xor_sync(0xffffffffu, bb.y, o);
                        float ox2 = __shfl_xor_sync(0xffffffffu, bb.z, o);
                        float oy2 = __shfl_xor_sync(0xffffffffu, bb.w, o);
                        if (ok_ > bk) { bk = ok_; bb = make_float4(ox1, oy1, ox2, oy2); }
                    }
                    if (bk == 0ULL) break;

                    if (lane == 0) { s_kbox[keeps] = bb; s_kok[keeps] = 1.f; }
                    // suppress registers vs new keep (self-IoU=1 covers ar==i)
                    float a1 = fmaxf(bb.z - bb.x, 0.f) * fmaxf(bb.w - bb.y, 0.f);
                    #pragma unroll
                    for (int r = 0; r < R_CAP; r++) {
                        if (k[r] != 0ULL) {
                            float lx = fmaxf(bb.x, bx[r].x), ly = fmaxf(bb.y, bx[r].y);
                            float rx = fminf(bb.z, bx[r].z), ry = fminf(bb.w, bx[r].w);
                            float inter = fmaxf(rx - lx, 0.f) * fmaxf(ry - ly, 0.f);
                            float a2 = fmaxf(bx[r].z - bx[r].x, 0.f) * fmaxf(bx[r].w - bx[r].y, 0.f);
                            if (inter / fmaxf(a1 + a2 - inter, 1e-9f) > IOU_TH) k[r] = 0ULL;
                        }
                    }
                    keeps++;
                }

                // write back keys so the next band sees suppressions
                if (keeps < TOPK) {
                    #pragma unroll
                    for (int r = 0; r < R_CAP; r++) {
                        int j = r * 32 + lane;
                        if (j < count) c_key[j] = k[r];
                    }
                }
            } else {
                // ================= smem fallback (rare) =================
                for (int ki = 0; ki < keeps; ki++) {
                    float4 kb = s_kbox[ki];
                    float a1 = fmaxf(kb.z - kb.x, 0.f) * fmaxf(kb.w - kb.y, 0.f);
                    for (int j = nold + lane; j < count; j += 32) {
                        float4 b = c_box[j];
                        float lx = fmaxf(kb.x, b.x), ly = fmaxf(kb.y, b.y);
                        float rx = fminf(kb.z, b.z), ry = fminf(kb.w, b.w);
                        float inter = fmaxf(rx - lx, 0.f) * fmaxf(ry - ly, 0.f);
                        float a2 = fmaxf(b.z - b.x, 0.f) * fmaxf(b.w - b.y, 0.f);
                        if (inter / fmaxf(a1 + a2 - inter, 1e-9f) > IOU_TH) c_key[j] = 0ULL;
                    }
                }
                __syncwarp();
                while (keeps < TOPK) {
                    unsigned long long bk = 0ULL; int bslot = 0;
                    for (int j = lane; j < count; j += 32) {
                        unsigned long long kk = c_key[j];
                        if (kk > bk) { bk = kk; bslot = j; }
                    }
                    #pragma unroll
                    for (int o = 16; o; o >>= 1) {
                        unsigned long long ok_ = __shfl_xor_sync(0xffffffffu, bk, o);
                        int                os_ = __shfl_xor_sync(0xffffffffu, bslot, o);
                        if (ok_ > bk) { bk = ok_; bslot = os_; }
                    }
                    if (bk == 0ULL) break;
                    float4 bb = c_box[bslot];
                    if (lane == 0) { s_kbox[keeps] = bb; s_kok[keeps] = 1.f; }
                    float a1 = fmaxf(bb.z - bb.x, 0.f) * fmaxf(bb.w - bb.y, 0.f);
                    for (int j = lane; j < count; j += 32) {
                        if (c_key[j] == 0ULL) continue;
                        float4 b = c_box[j];
                        float lx = fmaxf(bb.x, b.x), ly = fmaxf(bb.y, b.y);
                        float rx = fminf(bb.z, b.z), ry = fminf(bb.w, b.w);
                        float inter = fmaxf(rx - lx, 0.f) * fmaxf(ry - ly, 0.f);
                        float a2 = fmaxf(b.z - b.x, 0.f) * fmaxf(b.w - b.y, 0.f);
                        if (inter / fmaxf(a1 + a2 - inter, 1e-9f) > IOU_TH) c_key[j] = 0ULL;
                    }
                    __syncwarp();
                    keeps++;
                }
            }
            if (lane == 0) s_keeps = keeps;
        }
    }

    __syncthreads();
    if (tid < TOPK && tid >= s_keeps) s_kok[tid] = 0.f;
    __syncthreads();

    // ---- ROI-align: this block's (k, p) slice ----
    const int b = blockIdx.x;
    const int k = b / (ROI * ROI);
    const int p = b - k * (ROI * ROI);
    const int c = tid;

    float* o = out + b * NCHAN + c;

    if (s_kok[k] == 0.f) { *o = 0.f; return; }

    const float scale = (float)FH / 640.0f;
    const float4 kb = s_kbox[k];
    const float sx1 = kb.x * scale, sy1 = kb.y * scale;
    const float sx2 = kb.z * scale, sy2 = kb.w * scale;
    const float bw = fmaxf(sx2 - sx1, 1e-6f) / (float)ROI;
    const float bh = fmaxf(sy2 - sy1, 1e-6f) / (float)ROI;

    const int gy = p / ROI;
    const int gx = p - gy * ROI;
    const float yg = sy1 + ((float)gy + 0.5f) * bh;
    const float xg = sx1 + ((float)gx + 0.5f) * bw;

    const float fy = floorf(yg), fx = floorf(xg);
    const float wy = yg - fy,    wx = xg - fx;

    int y0  = min(max((int)fy, 0), FH - 1);
    int x0  = min(max((int)fx, 0), FH - 1);
    int y1i = min(y0 + 1, FH - 1);
    int x1i = min(x0 + 1, FH - 1);

    const float* f = feat + c * (FH * FH);
    float v00 = f[y0  * FH + x0 ];
    float v01 = f[y0  * FH + x1i];
    float v10 = f[y1i * FH + x0 ];
    float v11 = f[y1i * FH + x1i];

    *o = v00 * (1.f - wy) * (1.f - wx)
       + v01 * (1.f - wy) * wx
       + v10 * wy * (1.f - wx)
       + v11 * wy * wx;
}

// ---------------------------------------------------------------------------
extern "C" void kernel_launch(void* const* d_in, const int* in_sizes, int n_in,
                              void* d_out, int out_size)
{
    const float* pred = (const float*)d_in[0];
    const float* feat = (const float*)d_in[1];
    if (n_in >= 2 && in_sizes[0] != 5 * N_ANCH) {   // defensive swap on sizes
        pred = (const float*)d_in[1];
        feat = (const float*)d_in[0];
    }
    float* out = (float*)d_out;

    fused_kernel<<<TOPK * ROI * ROI, NT>>>(pred, feat, out);
}